// round 5
// baseline (speedup 1.0000x reference)
#include <cuda_runtime.h>
#include <cuda_bf16.h>
#include <math.h>
#include <stdint.h>

// Problem constants
#define BATCH 2
#define SEQ   4096
#define DIM   512
#define ROWS  (BATCH * SEQ)          // 8192

typedef __nv_bfloat16 bf16;

// ---------------------------------------------------------------------------
// Device scratch (static globals — no allocations)
// ---------------------------------------------------------------------------
__device__ bf16  g_xh[ROWS * DIM],  g_xl[ROWS * DIM];
__device__ bf16  g_wth[3 * DIM * DIM], g_wtl[3 * DIM * DIM];   // W^T hi/lo
__device__ bf16  g_Qh[ROWS * DIM],  g_Ql[ROWS * DIM];
__device__ bf16  g_Kh[ROWS * DIM],  g_Kl[ROWS * DIM];
__device__ bf16  g_Vth[(size_t)BATCH * DIM * SEQ], g_Vtl[(size_t)BATCH * DIM * SEQ]; // V^T [b][512][4096]
__device__ bf16  g_Ph[(size_t)BATCH * SEQ * SEQ], g_Pl[(size_t)BATCH * SEQ * SEQ];   // exp weights
__device__ float g_sum[ROWS];        // exp row sums (atomic)
__device__ float g_inv[ROWS];        // 1/rowsum

// ---------------------------------------------------------------------------
// helpers (baseline sm_80+ PTX only)
// ---------------------------------------------------------------------------
__device__ __forceinline__ uint32_t smem_u32(const void* p) {
    uint32_t a;
    asm("{ .reg .u64 t; cvta.to.shared.u64 t, %1; cvt.u32.u64 %0, t; }" : "=r"(a) : "l"(p));
    return a;
}
#define CP16(dst, src) \
    asm volatile("cp.async.cg.shared.global [%0], [%1], 16;" :: "r"(dst), "l"(src))
#define CP_COMMIT() asm volatile("cp.async.commit_group;" ::: "memory")
#define CP_WAIT1()  asm volatile("cp.async.wait_group 1;" ::: "memory")
#define CP_WAIT0()  asm volatile("cp.async.wait_group 0;" ::: "memory")

__device__ __forceinline__ void ldm_x4(uint32_t* r, uint32_t addr) {
    asm volatile("ldmatrix.sync.aligned.m8n8.x4.shared.b16 {%0,%1,%2,%3}, [%4];"
        : "=r"(r[0]), "=r"(r[1]), "=r"(r[2]), "=r"(r[3]) : "r"(addr));
}
__device__ __forceinline__ void mma_bf16(float* c, const uint32_t* a, const uint32_t* b) {
    asm volatile(
        "mma.sync.aligned.m16n8k16.row.col.f32.bf16.bf16.f32 "
        "{%0,%1,%2,%3}, {%4,%5,%6,%7}, {%8,%9}, {%0,%1,%2,%3};"
        : "+f"(c[0]), "+f"(c[1]), "+f"(c[2]), "+f"(c[3])
        : "r"(a[0]), "r"(a[1]), "r"(a[2]), "r"(a[3]), "r"(b[0]), "r"(b[1]));
}
__device__ __forceinline__ void store_split2(bf16* h, bf16* l, float a, float b) {
    bf16 h0 = __float2bfloat16(a), h1 = __float2bfloat16(b);
    __nv_bfloat162 hp, lp;
    hp.x = h0; hp.y = h1;
    lp.x = __float2bfloat16(a - __bfloat162float(h0));
    lp.y = __float2bfloat16(b - __bfloat162float(h1));
    *(__nv_bfloat162*)h = hp;
    *(__nv_bfloat162*)l = lp;
}

// Tiling: 256x128x32, 8 warps as 4(M) x 2(N), warp tile 64x64.
// smem rows padded to 80B (conflict-free for ldmatrix + cp.async).
#define BM 256
#define BN 128
#define PITCH 80
#define A_BYTES (BM * PITCH)                 // 20480
#define B_BYTES (BN * PITCH)                 // 10240
#define OFF_AH 0
#define OFF_AL A_BYTES
#define OFF_BH (2 * A_BYTES)
#define OFF_BL (2 * A_BYTES + B_BYTES)
#define STAGE  (2 * A_BYTES + 2 * B_BYTES)   // 61440
#define SMEM_DYN (2 * STAGE)                 // 122880

// ---------------------------------------------------------------------------
// NT GEMM via mma.sync: C[256x128] = sum_k A[m,k]*B[n,k], bf16 split 3-term.
// MODE 1: outF = val * rowscale[z*SEQ+row]           (context, normalized)
// MODE 2: outH/L = bf16 split [m,n]                  (Q/K projection)
// MODE 3: outH/L = bf16 split, n->(b,s): [b][m][s]   (V^T projection)
// MODE 4: e=exp(val*alpha) -> split store + atomic row sums (fused scores+softmax)
// ---------------------------------------------------------------------------
template <int MODE>
__global__ __launch_bounds__(256, 1)
void mma_gemm(const bf16* __restrict__ Ah, const bf16* __restrict__ Al,
              const bf16* __restrict__ Bh, const bf16* __restrict__ Bl,
              int K, size_t strideA, size_t strideB,
              float alpha, const float* __restrict__ rowscale, float* gsum,
              float* __restrict__ outF, size_t strideOut, int ldOut,
              bf16* __restrict__ outH, bf16* __restrict__ outL)
{
    extern __shared__ char smem[];
    const uint32_t sb = smem_u32(smem);
    const int tid  = threadIdx.x;
    const int lane = tid & 31;
    const int wid  = tid >> 5;
    const int wm   = wid & 3;         // 4 warps along M (64 rows each)
    const int wn   = wid >> 2;        // 2 warps along N (64 cols each)
    const int m0 = blockIdx.y * BM;
    const int n0 = blockIdx.x * BN;
    const int z  = blockIdx.z;

    const bf16* aH = Ah + z * strideA + (size_t)m0 * K;
    const bf16* aL = Al + z * strideA + (size_t)m0 * K;
    const bf16* bH = Bh + z * strideB + (size_t)n0 * K;
    const bf16* bL = Bl + z * strideB + (size_t)n0 * K;

    float acc[4][8][4];
#pragma unroll
    for (int i = 0; i < 4; i++)
#pragma unroll
        for (int j = 0; j < 8; j++)
#pragma unroll
            for (int q = 0; q < 4; q++) acc[i][j][q] = 0.f;

    const int nc = K >> 5;   // 32-wide k chunks

    // stage loader: A 1024 16B-chunks (4/thread/array), B 512 (2/thread/array)
    auto load_stage = [&](int s, int k0) {
        const uint32_t base = sb + s * STAGE;
#pragma unroll
        for (int i = 0; i < 4; i++) {
            const int c   = tid + i * 256;          // 0..1023
            const int row = c >> 2, kc = c & 3;
            const uint32_t doff = (uint32_t)(row * PITCH + kc * 16);
            const size_t   soff = (size_t)row * K + k0 + kc * 8;
            CP16(base + OFF_AH + doff, (const void*)(aH + soff));
            CP16(base + OFF_AL + doff, (const void*)(aL + soff));
        }
#pragma unroll
        for (int i = 0; i < 2; i++) {
            const int c   = tid + i * 256;          // 0..511
            const int row = c >> 2, kc = c & 3;
            const uint32_t doff = (uint32_t)(row * PITCH + kc * 16);
            const size_t   soff = (size_t)row * K + k0 + kc * 8;
            CP16(base + OFF_BH + doff, (const void*)(bH + soff));
            CP16(base + OFF_BL + doff, (const void*)(bL + soff));
        }
    };

    load_stage(0, 0);
    CP_COMMIT();

    for (int c = 0; c < nc; c++) {
        if (c + 1 < nc) {
            load_stage((c + 1) & 1, (c + 1) << 5);
            CP_COMMIT();
            CP_WAIT1();
        } else {
            CP_WAIT0();
        }
        __syncthreads();

        const uint32_t s0 = sb + (c & 1) * STAGE;
#pragma unroll
        for (int ks = 0; ks < 2; ks++) {
            uint32_t ah[4][4], al[4][4];
#pragma unroll
            for (int mi = 0; mi < 4; mi++) {
                const uint32_t ad = s0 +
                    (uint32_t)((wm * 64 + mi * 16 + (lane & 15)) * PITCH + ks * 32 + (lane >> 4) * 16);
                ldm_x4(ah[mi], ad + OFF_AH);
                ldm_x4(al[mi], ad + OFF_AL);
            }
#pragma unroll
            for (int bi = 0; bi < 4; bi++) {
                const uint32_t bd = s0 +
                    (uint32_t)((wn * 64 + bi * 16 + (lane & 15)) * PITCH + ks * 32 + (lane >> 4) * 16);
                uint32_t bh[4], bl[4];
                ldm_x4(bh, bd + OFF_BH);
                ldm_x4(bl, bd + OFF_BL);
#pragma unroll
                for (int n2 = 0; n2 < 2; n2++) {
                    const int ni = bi * 2 + n2;
                    uint32_t bbh[2] = { bh[n2], bh[2 + n2] };
                    uint32_t bbl[2] = { bl[n2], bl[2 + n2] };
#pragma unroll
                    for (int mi = 0; mi < 4; mi++) mma_bf16(acc[mi][ni], ah[mi], bbh);  // hh
#pragma unroll
                    for (int mi = 0; mi < 4; mi++) mma_bf16(acc[mi][ni], al[mi], bbh);  // lh
#pragma unroll
                    for (int mi = 0; mi < 4; mi++) mma_bf16(acc[mi][ni], ah[mi], bbl);  // hl
                }
            }
        }
        __syncthreads();
    }

    // ---- epilogue ----
    const int r  = lane >> 2;
    const int cq = (lane & 3) * 2;
#pragma unroll
    for (int mi = 0; mi < 4; mi++) {
        const int row0 = m0 + wm * 64 + mi * 16 + r;   // second half: row0+8
        float rs0 = 0.f, rs1 = 0.f;
#pragma unroll
        for (int ni = 0; ni < 8; ni++) {
            const int col = n0 + wn * 64 + ni * 8 + cq;
            float v00 = acc[mi][ni][0], v01 = acc[mi][ni][1];
            float v10 = acc[mi][ni][2], v11 = acc[mi][ni][3];
            if (MODE == 1) {
                const float s0 = rowscale[z * SEQ + row0];
                const float s1 = rowscale[z * SEQ + row0 + 8];
                float* o0 = outF + z * strideOut + (size_t)row0 * ldOut + col;
                float* o1 = outF + z * strideOut + (size_t)(row0 + 8) * ldOut + col;
                *(float2*)o0 = make_float2(v00 * s0, v01 * s0);
                *(float2*)o1 = make_float2(v10 * s1, v11 * s1);
            } else if (MODE == 2) {
                const size_t o0 = (size_t)row0 * ldOut + col;
                const size_t o1 = (size_t)(row0 + 8) * ldOut + col;
                store_split2(outH + o0, outL + o0, v00, v01);
                store_split2(outH + o1, outL + o1, v10, v11);
            } else if (MODE == 3) {  // columns are x-rows (batch, seq); rows are d
                const int b = col >> 12, s = col & 4095;
                const size_t o0 = (size_t)b * DIM * SEQ + (size_t)row0 * SEQ + s;
                const size_t o1 = o0 + (size_t)8 * SEQ;
                store_split2(outH + o0, outL + o0, v00, v01);
                store_split2(outH + o1, outL + o1, v10, v11);
            } else {  // MODE 4: fused exp + split + row-sum
                float e00 = __expf(v00 * alpha), e01 = __expf(v01 * alpha);
                float e10 = __expf(v10 * alpha), e11 = __expf(v11 * alpha);
                rs0 += e00 + e01;
                rs1 += e10 + e11;
                const size_t base = (size_t)z * SEQ * SEQ;
                const size_t o0 = base + (size_t)row0 * SEQ + col;
                const size_t o1 = base + (size_t)(row0 + 8) * SEQ + col;
                store_split2(outH + o0, outL + o0, e00, e01);
                store_split2(outH + o1, outL + o1, e10, e11);
            }
        }
        if (MODE == 4) {
            rs0 += __shfl_xor_sync(0xffffffffu, rs0, 1);
            rs0 += __shfl_xor_sync(0xffffffffu, rs0, 2);
            rs1 += __shfl_xor_sync(0xffffffffu, rs1, 1);
            rs1 += __shfl_xor_sync(0xffffffffu, rs1, 2);
            if ((lane & 3) == 0) {
                atomicAdd(&gsum[z * SEQ + row0], rs0);
                atomicAdd(&gsum[z * SEQ + row0 + 8], rs1);
            }
        }
    }
}

// ---------------------------------------------------------------------------
// prep kernels
// ---------------------------------------------------------------------------
__global__ void split_f32(const float* __restrict__ in, bf16* __restrict__ h,
                          bf16* __restrict__ l, int n4)
{
    int i = blockIdx.x * blockDim.x + threadIdx.x;
    if (i >= n4) return;
    float4 v = ((const float4*)in)[i];
    bf16 h0 = __float2bfloat16(v.x), h1 = __float2bfloat16(v.y);
    bf16 h2 = __float2bfloat16(v.z), h3 = __float2bfloat16(v.w);
    __nv_bfloat162 hp0, hp1, lp0, lp1;
    hp0.x = h0; hp0.y = h1; hp1.x = h2; hp1.y = h3;
    lp0.x = __float2bfloat16(v.x - __bfloat162float(h0));
    lp0.y = __float2bfloat16(v.y - __bfloat162float(h1));
    lp1.x = __float2bfloat16(v.z - __bfloat162float(h2));
    lp1.y = __float2bfloat16(v.w - __bfloat162float(h3));
    ((__nv_bfloat162*)h)[i * 2 + 0] = hp0;
    ((__nv_bfloat162*)h)[i * 2 + 1] = hp1;
    ((__nv_bfloat162*)l)[i * 2 + 0] = lp0;
    ((__nv_bfloat162*)l)[i * 2 + 1] = lp1;
}

__global__ void transpose_split_w(const float* __restrict__ W,
                                  bf16* __restrict__ th, bf16* __restrict__ tl)
{
    int id = blockIdx.x * blockDim.x + threadIdx.x;   // 512*512
    if (id >= DIM * DIM) return;
    int k = id >> 9, n = id & 511;
    float v = W[id];
    bf16 h = __float2bfloat16(v);
    bf16 l = __float2bfloat16(v - __bfloat162float(h));
    th[n * DIM + k] = h;
    tl[n * DIM + k] = l;
}

__global__ void zero_sums(float* __restrict__ s)
{
    int i = blockIdx.x * blockDim.x + threadIdx.x;
    if (i < ROWS) s[i] = 0.f;
}

__global__ void invert_sums(const float* __restrict__ s, float* __restrict__ inv)
{
    int i = blockIdx.x * blockDim.x + threadIdx.x;
    if (i < ROWS) inv[i] = 1.0f / s[i];
}

// ---------------------------------------------------------------------------
extern "C" void kernel_launch(void* const* d_in, const int* in_sizes, int n_in,
                              void* d_out, int out_size)
{
    const float* x  = (const float*)d_in[0];
    const float* Wq = (const float*)d_in[1];
    const float* Wk = (const float*)d_in[2];
    const float* Wv = (const float*)d_in[3];
    float* out = (float*)d_out;

    bf16 *xh, *xl, *wth, *wtl, *Qh, *Ql, *Kh, *Kl, *Vth, *Vtl, *Ph, *Pl;
    float *sum, *inv;
    cudaGetSymbolAddress((void**)&xh,  g_xh);  cudaGetSymbolAddress((void**)&xl,  g_xl);
    cudaGetSymbolAddress((void**)&wth, g_wth); cudaGetSymbolAddress((void**)&wtl, g_wtl);
    cudaGetSymbolAddress((void**)&Qh,  g_Qh);  cudaGetSymbolAddress((void**)&Ql,  g_Ql);
    cudaGetSymbolAddress((void**)&Kh,  g_Kh);  cudaGetSymbolAddress((void**)&Kl,  g_Kl);
    cudaGetSymbolAddress((void**)&Vth, g_Vth); cudaGetSymbolAddress((void**)&Vtl, g_Vtl);
    cudaGetSymbolAddress((void**)&Ph,  g_Ph);  cudaGetSymbolAddress((void**)&Pl,  g_Pl);
    cudaGetSymbolAddress((void**)&sum, g_sum);
    cudaGetSymbolAddress((void**)&inv, g_inv);

    cudaFuncSetAttribute(mma_gemm<1>, cudaFuncAttributeMaxDynamicSharedMemorySize, SMEM_DYN);
    cudaFuncSetAttribute(mma_gemm<2>, cudaFuncAttributeMaxDynamicSharedMemorySize, SMEM_DYN);
    cudaFuncSetAttribute(mma_gemm<3>, cudaFuncAttributeMaxDynamicSharedMemorySize, SMEM_DYN);
    cudaFuncSetAttribute(mma_gemm<4>, cudaFuncAttributeMaxDynamicSharedMemorySize, SMEM_DYN);

    const float inv_sqrt_d = 0.04419417382415922f;  // 1/sqrt(512)

    // 0) zero row sums + split inputs to bf16 hi/lo
    zero_sums<<<(ROWS + 255) / 256, 256>>>(sum);
    split_f32<<<(ROWS * DIM / 4 + 255) / 256, 256>>>(x, xh, xl, ROWS * DIM / 4);
    transpose_split_w<<<(DIM * DIM + 255) / 256, 256>>>(Wq, wth + 0 * DIM * DIM, wtl + 0 * DIM * DIM);
    transpose_split_w<<<(DIM * DIM + 255) / 256, 256>>>(Wk, wth + 1 * DIM * DIM, wtl + 1 * DIM * DIM);
    transpose_split_w<<<(DIM * DIM + 255) / 256, 256>>>(Wv, wth + 2 * DIM * DIM, wtl + 2 * DIM * DIM);

    // 1) projections (NT). Q, K: x @ Wt. V: Wt x x^T -> V^T directly.
    {
        dim3 gq(DIM / BN, ROWS / BM, 1);
        mma_gemm<2><<<gq, 256, SMEM_DYN>>>(xh, xl, wth + 0 * DIM * DIM, wtl + 0 * DIM * DIM,
            DIM, 0, 0, 1.f, nullptr, nullptr, nullptr, 0, DIM, Qh, Ql);
        mma_gemm<2><<<gq, 256, SMEM_DYN>>>(xh, xl, wth + 1 * DIM * DIM, wtl + 1 * DIM * DIM,
            DIM, 0, 0, 1.f, nullptr, nullptr, nullptr, 0, DIM, Kh, Kl);
        dim3 gv(ROWS / BN, DIM / BM, 1);
        mma_gemm<3><<<gv, 256, SMEM_DYN>>>(wth + 2 * DIM * DIM, wtl + 2 * DIM * DIM, xh, xl,
            DIM, 0, 0, 1.f, nullptr, nullptr, nullptr, 0, 0, Vth, Vtl);
    }

    // 2) fused scores + softmax-exp: P = exp(QK^T/sqrt(d)) + atomic row sums
    {
        dim3 g(SEQ / BN, SEQ / BM, BATCH);
        mma_gemm<4><<<g, 256, SMEM_DYN>>>(Qh, Ql, Kh, Kl,
            DIM, (size_t)SEQ * DIM, (size_t)SEQ * DIM,
            inv_sqrt_d, nullptr, sum, nullptr, 0, 0, Ph, Pl);
    }

    // 3) invert row sums
    invert_sums<<<(ROWS + 255) / 256, 256>>>(sum, inv);

    // 4) context = diag(1/rowsum) * (P @ V), B = V^T (K-major)
    {
        dim3 g(DIM / BN, SEQ / BM, BATCH);
        mma_gemm<1><<<g, 256, SMEM_DYN>>>(Ph, Pl, Vth, Vtl,
            SEQ, (size_t)SEQ * SEQ, (size_t)DIM * SEQ,
            1.f, inv, nullptr, out, (size_t)SEQ * DIM, DIM, nullptr, nullptr);
    }
}

// round 6
// speedup vs baseline: 1.5365x; 1.5365x over previous
#include <cuda_runtime.h>
#include <cuda_bf16.h>
#include <math.h>
#include <stdint.h>

// Problem constants
#define BATCH 2
#define SEQ   4096
#define DIM   512
#define ROWS  (BATCH * SEQ)          // 8192

typedef __nv_bfloat16 bf16;

// ---------------------------------------------------------------------------
// Device scratch (static globals — no allocations)
// ---------------------------------------------------------------------------
__device__ bf16  g_xh[ROWS * DIM],  g_xl[ROWS * DIM];
__device__ bf16  g_wth[3 * DIM * DIM], g_wtl[3 * DIM * DIM];   // W^T hi/lo
__device__ bf16  g_Qh[ROWS * DIM],  g_Ql[ROWS * DIM];
__device__ bf16  g_Kh[ROWS * DIM],  g_Kl[ROWS * DIM];
__device__ bf16  g_Vth[(size_t)BATCH * DIM * SEQ], g_Vtl[(size_t)BATCH * DIM * SEQ]; // V^T [b][512][4096]
__device__ bf16  g_Ph[(size_t)BATCH * SEQ * SEQ], g_Pl[(size_t)BATCH * SEQ * SEQ];   // exp weights
__device__ float g_sum[ROWS];        // exp row sums (atomic)
__device__ float g_inv[ROWS];        // 1/rowsum

// ---------------------------------------------------------------------------
// helpers (baseline sm_80+ PTX only — NO tcgen05 / 'a'-gated features)
// ---------------------------------------------------------------------------
__device__ __forceinline__ uint32_t smem_u32(const void* p) {
    uint32_t a;
    asm("{ .reg .u64 t; cvta.to.shared.u64 t, %1; cvt.u32.u64 %0, t; }" : "=r"(a) : "l"(p));
    return a;
}
#define CP16(dst, src) \
    asm volatile("cp.async.cg.shared.global [%0], [%1], 16;" :: "r"(dst), "l"(src))
#define CP_COMMIT() asm volatile("cp.async.commit_group;" ::: "memory")
#define CP_WAIT1()  asm volatile("cp.async.wait_group 1;" ::: "memory")
#define CP_WAIT0()  asm volatile("cp.async.wait_group 0;" ::: "memory")

__device__ __forceinline__ void ldm_x4(uint32_t* r, uint32_t addr) {
    asm volatile("ldmatrix.sync.aligned.m8n8.x4.shared.b16 {%0,%1,%2,%3}, [%4];"
        : "=r"(r[0]), "=r"(r[1]), "=r"(r[2]), "=r"(r[3]) : "r"(addr));
}
__device__ __forceinline__ void mma_bf16(float* c, const uint32_t* a, const uint32_t* b) {
    asm volatile(
        "mma.sync.aligned.m16n8k16.row.col.f32.bf16.bf16.f32 "
        "{%0,%1,%2,%3}, {%4,%5,%6,%7}, {%8,%9}, {%0,%1,%2,%3};"
        : "+f"(c[0]), "+f"(c[1]), "+f"(c[2]), "+f"(c[3])
        : "r"(a[0]), "r"(a[1]), "r"(a[2]), "r"(a[3]), "r"(b[0]), "r"(b[1]));
}
__device__ __forceinline__ void store_split2(bf16* h, bf16* l, float a, float b) {
    bf16 h0 = __float2bfloat16(a), h1 = __float2bfloat16(b);
    __nv_bfloat162 hp, lp;
    hp.x = h0; hp.y = h1;
    lp.x = __float2bfloat16(a - __bfloat162float(h0));
    lp.y = __float2bfloat16(b - __bfloat162float(h1));
    *(__nv_bfloat162*)h = hp;
    *(__nv_bfloat162*)l = lp;
}

// smem layout: per stage 4 arrays (Ah, Al, Bh, Bl), each 128 rows x 80 bytes
// (R4-proven config: 2 CTAs/SM, 16 warps — do NOT enlarge tiles.)
#define ARR    10240
#define STAGE  40960
#define SMEM_DYN (2 * STAGE)   // 81920 bytes

// ---------------------------------------------------------------------------
// NT GEMM via mma.sync: C[128x128] = sum_k A[m,k]*B[n,k], bf16 split 3-term.
// MODE 1: outF = val * rowscale[z*SEQ+row]            (context, normalized)
// MODE 2: outH/L = bf16 split [m,n]                   (Q/K projection)
// MODE 3: outH/L = bf16 split, n->(b,s): [b][m][s]    (V^T projection)
// MODE 4: e=exp(val*alpha) -> split store + atomic row sums (fused scores+softmax)
// ---------------------------------------------------------------------------
template <int MODE>
__global__ __launch_bounds__(256, 2)
void mma_gemm(const bf16* __restrict__ Ah, const bf16* __restrict__ Al,
              const bf16* __restrict__ Bh, const bf16* __restrict__ Bl,
              int K, size_t strideA, size_t strideB,
              float alpha, const float* __restrict__ rowscale, float* gsum,
              float* __restrict__ outF, size_t strideOut, int ldOut,
              bf16* __restrict__ outH, bf16* __restrict__ outL)
{
    extern __shared__ char smem[];
    const uint32_t sb = smem_u32(smem);
    const int tid  = threadIdx.x;
    const int lane = tid & 31;
    const int wid  = tid >> 5;
    const int wm   = wid & 1;         // 2 warps along M (64 rows each)
    const int wn   = wid >> 1;        // 4 warps along N (32 cols each)
    const int m0 = blockIdx.y * 128;
    const int n0 = blockIdx.x * 128;
    const int z  = blockIdx.z;

    const bf16* aH = Ah + z * strideA + (size_t)m0 * K;
    const bf16* aL = Al + z * strideA + (size_t)m0 * K;
    const bf16* bH = Bh + z * strideB + (size_t)n0 * K;
    const bf16* bL = Bl + z * strideB + (size_t)n0 * K;

    float acc[4][4][4];
#pragma unroll
    for (int i = 0; i < 4; i++)
#pragma unroll
        for (int j = 0; j < 4; j++)
#pragma unroll
            for (int q = 0; q < 4; q++) acc[i][j][q] = 0.f;

    const int nc = K >> 5;   // 32-wide k chunks

    // ---- stage loader: 8 x 16B cp.async per thread ----
    auto load_stage = [&](int s, int k0) {
        const uint32_t base = sb + s * STAGE;
#pragma unroll
        for (int i = 0; i < 2; i++) {
            const int c   = tid + i * 256;
            const int row = c >> 2, kc = c & 3;
            const uint32_t doff = (uint32_t)(row * 80 + kc * 16);
            const size_t   soff = (size_t)row * K + k0 + kc * 8;
            CP16(base + 0 * ARR + doff, (const void*)(aH + soff));
            CP16(base + 1 * ARR + doff, (const void*)(aL + soff));
            CP16(base + 2 * ARR + doff, (const void*)(bH + soff));
            CP16(base + 3 * ARR + doff, (const void*)(bL + soff));
        }
    };

    load_stage(0, 0);
    CP_COMMIT();

    for (int c = 0; c < nc; c++) {
        if (c + 1 < nc) {
            load_stage((c + 1) & 1, (c + 1) << 5);
            CP_COMMIT();
            CP_WAIT1();
        } else {
            CP_WAIT0();
        }
        __syncthreads();

        const uint32_t s0 = sb + (c & 1) * STAGE;
#pragma unroll
        for (int ks = 0; ks < 2; ks++) {
            uint32_t ah[4][4], al[4][4];
#pragma unroll
            for (int mi = 0; mi < 4; mi++) {
                const uint32_t ad = s0 +
                    (uint32_t)((wm * 64 + mi * 16 + (lane & 15)) * 80 + ks * 32 + (lane >> 4) * 16);
                ldm_x4(ah[mi], ad);
                ldm_x4(al[mi], ad + ARR);
            }
#pragma unroll
            for (int bi = 0; bi < 2; bi++) {
                const uint32_t bd = s0 + 2 * ARR +
                    (uint32_t)((wn * 32 + bi * 16 + (lane & 15)) * 80 + ks * 32 + (lane >> 4) * 16);
                uint32_t bh[4], bl[4];
                ldm_x4(bh, bd);
                ldm_x4(bl, bd + ARR);
#pragma unroll
                for (int n2 = 0; n2 < 2; n2++) {
                    const int ni = bi * 2 + n2;
                    uint32_t bbh[2] = { bh[n2], bh[2 + n2] };
                    uint32_t bbl[2] = { bl[n2], bl[2 + n2] };
#pragma unroll
                    for (int mi = 0; mi < 4; mi++) mma_bf16(acc[mi][ni], ah[mi], bbh);  // hh
#pragma unroll
                    for (int mi = 0; mi < 4; mi++) mma_bf16(acc[mi][ni], al[mi], bbh);  // lh
#pragma unroll
                    for (int mi = 0; mi < 4; mi++) mma_bf16(acc[mi][ni], ah[mi], bbl);  // hl
                }
            }
        }
        __syncthreads();
    }

    // ---- epilogue ----
    const int r  = lane >> 2;
    const int cq = (lane & 3) * 2;
#pragma unroll
    for (int mi = 0; mi < 4; mi++) {
        const int row0 = m0 + wm * 64 + mi * 16 + r;   // second half: row0+8
        float rs0 = 0.f, rs1 = 0.f;
#pragma unroll
        for (int ni = 0; ni < 4; ni++) {
            const int col = n0 + wn * 32 + ni * 8 + cq;
            float v00 = acc[mi][ni][0], v01 = acc[mi][ni][1];
            float v10 = acc[mi][ni][2], v11 = acc[mi][ni][3];
            if (MODE == 1) {
                const float s0 = rowscale[z * SEQ + row0];
                const float s1 = rowscale[z * SEQ + row0 + 8];
                float* o0 = outF + z * strideOut + (size_t)row0 * ldOut + col;
                float* o1 = outF + z * strideOut + (size_t)(row0 + 8) * ldOut + col;
                *(float2*)o0 = make_float2(v00 * s0, v01 * s0);
                *(float2*)o1 = make_float2(v10 * s1, v11 * s1);
            } else if (MODE == 2) {
                const size_t o0 = (size_t)row0 * ldOut + col;
                const size_t o1 = (size_t)(row0 + 8) * ldOut + col;
                store_split2(outH + o0, outL + o0, v00, v01);
                store_split2(outH + o1, outL + o1, v10, v11);
            } else if (MODE == 3) {  // columns are x-rows (batch, seq); rows are d
                const int b = col >> 12, s = col & 4095;
                const size_t o0 = (size_t)b * DIM * SEQ + (size_t)row0 * SEQ + s;
                const size_t o1 = o0 + (size_t)8 * SEQ;
                store_split2(outH + o0, outL + o0, v00, v01);
                store_split2(outH + o1, outL + o1, v10, v11);
            } else {  // MODE 4: fused exp + split + row-sum
                float e00 = __expf(v00 * alpha), e01 = __expf(v01 * alpha);
                float e10 = __expf(v10 * alpha), e11 = __expf(v11 * alpha);
                rs0 += e00 + e01;
                rs1 += e10 + e11;
                const size_t base = (size_t)z * SEQ * SEQ;
                const size_t o0 = base + (size_t)row0 * SEQ + col;
                const size_t o1 = base + (size_t)(row0 + 8) * SEQ + col;
                store_split2(outH + o0, outL + o0, e00, e01);
                store_split2(outH + o1, outL + o1, e10, e11);
            }
        }
        if (MODE == 4) {
            rs0 += __shfl_xor_sync(0xffffffffu, rs0, 1);
            rs0 += __shfl_xor_sync(0xffffffffu, rs0, 2);
            rs1 += __shfl_xor_sync(0xffffffffu, rs1, 1);
            rs1 += __shfl_xor_sync(0xffffffffu, rs1, 2);
            if ((lane & 3) == 0) {
                atomicAdd(&gsum[z * SEQ + row0], rs0);
                atomicAdd(&gsum[z * SEQ + row0 + 8], rs1);
            }
        }
    }
}

// ---------------------------------------------------------------------------
// prep kernels
// ---------------------------------------------------------------------------
__global__ void split_f32(const float* __restrict__ in, bf16* __restrict__ h,
                          bf16* __restrict__ l, int n4)
{
    int i = blockIdx.x * blockDim.x + threadIdx.x;
    if (i >= n4) return;
    float4 v = ((const float4*)in)[i];
    bf16 h0 = __float2bfloat16(v.x), h1 = __float2bfloat16(v.y);
    bf16 h2 = __float2bfloat16(v.z), h3 = __float2bfloat16(v.w);
    __nv_bfloat162 hp0, hp1, lp0, lp1;
    hp0.x = h0; hp0.y = h1; hp1.x = h2; hp1.y = h3;
    lp0.x = __float2bfloat16(v.x - __bfloat162float(h0));
    lp0.y = __float2bfloat16(v.y - __bfloat162float(h1));
    lp1.x = __float2bfloat16(v.z - __bfloat162float(h2));
    lp1.y = __float2bfloat16(v.w - __bfloat162float(h3));
    ((__nv_bfloat162*)h)[i * 2 + 0] = hp0;
    ((__nv_bfloat162*)h)[i * 2 + 1] = hp1;
    ((__nv_bfloat162*)l)[i * 2 + 0] = lp0;
    ((__nv_bfloat162*)l)[i * 2 + 1] = lp1;
}

__global__ void transpose_split_w(const float* __restrict__ W,
                                  bf16* __restrict__ th, bf16* __restrict__ tl)
{
    int id = blockIdx.x * blockDim.x + threadIdx.x;   // 512*512
    if (id >= DIM * DIM) return;
    int k = id >> 9, n = id & 511;
    float v = W[id];
    bf16 h = __float2bfloat16(v);
    bf16 l = __float2bfloat16(v - __bfloat162float(h));
    th[n * DIM + k] = h;
    tl[n * DIM + k] = l;
}

__global__ void zero_sums(float* __restrict__ s)
{
    int i = blockIdx.x * blockDim.x + threadIdx.x;
    if (i < ROWS) s[i] = 0.f;
}

__global__ void invert_sums(const float* __restrict__ s, float* __restrict__ inv)
{
    int i = blockIdx.x * blockDim.x + threadIdx.x;
    if (i < ROWS) inv[i] = 1.0f / s[i];
}

// ---------------------------------------------------------------------------
extern "C" void kernel_launch(void* const* d_in, const int* in_sizes, int n_in,
                              void* d_out, int out_size)
{
    const float* x  = (const float*)d_in[0];
    const float* Wq = (const float*)d_in[1];
    const float* Wk = (const float*)d_in[2];
    const float* Wv = (const float*)d_in[3];
    float* out = (float*)d_out;

    bf16 *xh, *xl, *wth, *wtl, *Qh, *Ql, *Kh, *Kl, *Vth, *Vtl, *Ph, *Pl;
    float *sum, *inv;
    cudaGetSymbolAddress((void**)&xh,  g_xh);  cudaGetSymbolAddress((void**)&xl,  g_xl);
    cudaGetSymbolAddress((void**)&wth, g_wth); cudaGetSymbolAddress((void**)&wtl, g_wtl);
    cudaGetSymbolAddress((void**)&Qh,  g_Qh);  cudaGetSymbolAddress((void**)&Ql,  g_Ql);
    cudaGetSymbolAddress((void**)&Kh,  g_Kh);  cudaGetSymbolAddress((void**)&Kl,  g_Kl);
    cudaGetSymbolAddress((void**)&Vth, g_Vth); cudaGetSymbolAddress((void**)&Vtl, g_Vtl);
    cudaGetSymbolAddress((void**)&Ph,  g_Ph);  cudaGetSymbolAddress((void**)&Pl,  g_Pl);
    cudaGetSymbolAddress((void**)&sum, g_sum);
    cudaGetSymbolAddress((void**)&inv, g_inv);

    cudaFuncSetAttribute(mma_gemm<1>, cudaFuncAttributeMaxDynamicSharedMemorySize, SMEM_DYN);
    cudaFuncSetAttribute(mma_gemm<2>, cudaFuncAttributeMaxDynamicSharedMemorySize, SMEM_DYN);
    cudaFuncSetAttribute(mma_gemm<3>, cudaFuncAttributeMaxDynamicSharedMemorySize, SMEM_DYN);
    cudaFuncSetAttribute(mma_gemm<4>, cudaFuncAttributeMaxDynamicSharedMemorySize, SMEM_DYN);

    const float inv_sqrt_d = 0.04419417382415922f;  // 1/sqrt(512)

    // 0) zero row sums + split inputs to bf16 hi/lo
    zero_sums<<<(ROWS + 255) / 256, 256>>>(sum);
    split_f32<<<(ROWS * DIM / 4 + 255) / 256, 256>>>(x, xh, xl, ROWS * DIM / 4);
    transpose_split_w<<<(DIM * DIM + 255) / 256, 256>>>(Wq, wth + 0 * DIM * DIM, wtl + 0 * DIM * DIM);
    transpose_split_w<<<(DIM * DIM + 255) / 256, 256>>>(Wk, wth + 1 * DIM * DIM, wtl + 1 * DIM * DIM);
    transpose_split_w<<<(DIM * DIM + 255) / 256, 256>>>(Wv, wth + 2 * DIM * DIM, wtl + 2 * DIM * DIM);

    // 1) projections (NT). Q, K: x @ Wt. V: Wt x x^T -> V^T directly.
    {
        dim3 gq(DIM / 128, ROWS / 128, 1);
        mma_gemm<2><<<gq, 256, SMEM_DYN>>>(xh, xl, wth + 0 * DIM * DIM, wtl + 0 * DIM * DIM,
            DIM, 0, 0, 1.f, nullptr, nullptr, nullptr, 0, DIM, Qh, Ql);
        mma_gemm<2><<<gq, 256, SMEM_DYN>>>(xh, xl, wth + 1 * DIM * DIM, wtl + 1 * DIM * DIM,
            DIM, 0, 0, 1.f, nullptr, nullptr, nullptr, 0, DIM, Kh, Kl);
        dim3 gv(ROWS / 128, DIM / 128, 1);
        mma_gemm<3><<<gv, 256, SMEM_DYN>>>(wth + 2 * DIM * DIM, wtl + 2 * DIM * DIM, xh, xl,
            DIM, 0, 0, 1.f, nullptr, nullptr, nullptr, 0, 0, Vth, Vtl);
    }

    // 2) fused scores + softmax-exp: P = exp(QK^T/sqrt(d)) + atomic row sums
    {
        dim3 g(SEQ / 128, SEQ / 128, BATCH);
        mma_gemm<4><<<g, 256, SMEM_DYN>>>(Qh, Ql, Kh, Kl,
            DIM, (size_t)SEQ * DIM, (size_t)SEQ * DIM,
            inv_sqrt_d, nullptr, sum, nullptr, 0, 0, Ph, Pl);
    }

    // 3) invert row sums
    invert_sums<<<(ROWS + 255) / 256, 256>>>(sum, inv);

    // 4) context = diag(1/rowsum) * (P @ V), B = V^T (K-major)
    {
        dim3 g(DIM / 128, SEQ / 128, BATCH);
        mma_gemm<1><<<g, 256, SMEM_DYN>>>(Ph, Pl, Vth, Vtl,
            SEQ, (size_t)SEQ * SEQ, (size_t)DIM * SEQ,
            1.f, inv, nullptr, out, (size_t)SEQ * DIM, DIM, nullptr, nullptr);
    }
}

// round 7
// speedup vs baseline: 1.9980x; 1.3003x over previous
#include <cuda_runtime.h>
#include <cuda_bf16.h>
#include <cuda_fp16.h>
#include <math.h>
#include <stdint.h>

// Problem constants
#define BATCH 2
#define SEQ   4096
#define DIM   512
#define ROWS  (BATCH * SEQ)          // 8192

typedef __nv_bfloat16 bf16;

// ---------------------------------------------------------------------------
// Device scratch (static globals — no allocations)
// ---------------------------------------------------------------------------
__device__ bf16   g_xh[ROWS * DIM],  g_xl[ROWS * DIM];          // x split (proj A operand)
__device__ bf16   g_wth[3 * DIM * DIM], g_wtl[3 * DIM * DIM];   // W^T hi/lo (proj B operand)
__device__ __half g_Qh[ROWS * DIM],  g_Ql[ROWS * DIM];          // Q fp16 hi/lo (scores A)
__device__ __half g_Kh[ROWS * DIM];                              // K fp16 hi only (scores B)
__device__ __half g_Vth[(size_t)BATCH * DIM * SEQ];              // V^T fp16 hi only (context B)
__device__ __half g_Ph[(size_t)BATCH * SEQ * SEQ];               // P fp16 hi (context A)
__device__ __half g_Pl[(size_t)BATCH * SEQ * SEQ];               // P fp16 lo
__device__ float  g_sum[ROWS];       // exp row sums (atomic)
__device__ float  g_inv[ROWS];       // 1/rowsum

// ---------------------------------------------------------------------------
// helpers (baseline sm_80+ PTX only — NO tcgen05 / 'a'-gated features)
// ---------------------------------------------------------------------------
__device__ __forceinline__ uint32_t smem_u32(const void* p) {
    uint32_t a;
    asm("{ .reg .u64 t; cvta.to.shared.u64 t, %1; cvt.u32.u64 %0, t; }" : "=r"(a) : "l"(p));
    return a;
}
#define CP16(dst, src) \
    asm volatile("cp.async.cg.shared.global [%0], [%1], 16;" :: "r"(dst), "l"(src))
#define CP_COMMIT() asm volatile("cp.async.commit_group;" ::: "memory")
#define CP_WAIT1()  asm volatile("cp.async.wait_group 1;" ::: "memory")
#define CP_WAIT0()  asm volatile("cp.async.wait_group 0;" ::: "memory")

__device__ __forceinline__ void ldm_x4(uint32_t* r, uint32_t addr) {
    asm volatile("ldmatrix.sync.aligned.m8n8.x4.shared.b16 {%0,%1,%2,%3}, [%4];"
        : "=r"(r[0]), "=r"(r[1]), "=r"(r[2]), "=r"(r[3]) : "r"(addr));
}
__device__ __forceinline__ void mma_bf16(float* c, const uint32_t* a, const uint32_t* b) {
    asm volatile(
        "mma.sync.aligned.m16n8k16.row.col.f32.bf16.bf16.f32 "
        "{%0,%1,%2,%3}, {%4,%5,%6,%7}, {%8,%9}, {%0,%1,%2,%3};"
        : "+f"(c[0]), "+f"(c[1]), "+f"(c[2]), "+f"(c[3])
        : "r"(a[0]), "r"(a[1]), "r"(a[2]), "r"(a[3]), "r"(b[0]), "r"(b[1]));
}
__device__ __forceinline__ void mma_f16(float* c, const uint32_t* a, const uint32_t* b) {
    asm volatile(
        "mma.sync.aligned.m16n8k16.row.col.f32.f16.f16.f32 "
        "{%0,%1,%2,%3}, {%4,%5,%6,%7}, {%8,%9}, {%0,%1,%2,%3};"
        : "+f"(c[0]), "+f"(c[1]), "+f"(c[2]), "+f"(c[3])
        : "r"(a[0]), "r"(a[1]), "r"(a[2]), "r"(a[3]), "r"(b[0]), "r"(b[1]));
}
// fp16 split store: h = rn(x), l = rn(x - h)
__device__ __forceinline__ void store_split2_h(__half* h, __half* l, float a, float b) {
    __half h0 = __float2half_rn(a), h1 = __float2half_rn(b);
    __half l0 = __float2half_rn(a - __half2float(h0));
    __half l1 = __float2half_rn(b - __half2float(h1));
    *(__half2*)h = __halves2half2(h0, h1);
    *(__half2*)l = __halves2half2(l0, l1);
}
__device__ __forceinline__ void store2_h(__half* o, float a, float b) {
    *(__half2*)o = __halves2half2(__float2half_rn(a), __float2half_rn(b));
}

// smem: per-array 128 rows x 80 bytes; 3-term stages have 4 arrays, 2-term 3.
#define ARR 10240

// ---------------------------------------------------------------------------
// NT GEMM via mma.sync: C[128x128] = sum_k A[m,k]*B[n,k] (16-bit operands).
// MODE 0: bf16 3-term proj, z=0 -> Q split fp16, z=1 -> K hi-only fp16
// MODE 3: bf16 3-term proj (A=W^T, B=x): V^T hi-only fp16 [b][d][s]
// MODE 4: fp16 2-term scores: e=exp(val*alpha) -> split fp16 + atomic row sums
// MODE 1: fp16 2-term context: outF = val * rowscale[z*SEQ+row]
// ---------------------------------------------------------------------------
template <int MODE>
__global__ __launch_bounds__(256, 2)
void mma_gemm(const uint16_t* __restrict__ Ah, const uint16_t* __restrict__ Al,
              const uint16_t* __restrict__ Bh, const uint16_t* __restrict__ Bl,
              int K, size_t strideA, size_t strideB,
              float alpha, const float* __restrict__ rowscale, float* gsum,
              float* __restrict__ outF, size_t strideOut, int ldOut,
              __half* __restrict__ outH, __half* __restrict__ outL,
              __half* __restrict__ outH2)
{
    constexpr int  TERMS = (MODE == 0 || MODE == 3) ? 3 : 2;
    constexpr int  NARR  = (TERMS == 3) ? 4 : 3;
    constexpr int  STG   = NARR * ARR;

    extern __shared__ char smem[];
    const uint32_t sb = smem_u32(smem);
    const int tid  = threadIdx.x;
    const int lane = tid & 31;
    const int wid  = tid >> 5;
    const int wm   = wid & 1;         // 2 warps along M (64 rows each)
    const int wn   = wid >> 1;        // 4 warps along N (32 cols each)
    const int m0 = blockIdx.y * 128;
    const int n0 = blockIdx.x * 128;
    const int z  = blockIdx.z;

    const uint16_t* aH = Ah + z * strideA + (size_t)m0 * K;
    const uint16_t* aL = Al + z * strideA + (size_t)m0 * K;
    const uint16_t* bH = Bh + z * strideB + (size_t)n0 * K;
    const uint16_t* bL = (TERMS == 3) ? (Bl + z * strideB + (size_t)n0 * K) : nullptr;

    float acc[4][4][4];
#pragma unroll
    for (int i = 0; i < 4; i++)
#pragma unroll
        for (int j = 0; j < 4; j++)
#pragma unroll
            for (int q = 0; q < 4; q++) acc[i][j][q] = 0.f;

    const int nc = K >> 5;   // 32-wide k chunks

    // stage loader: 16B cp.async per thread per array (2 chunks each)
    auto load_stage = [&](int s, int k0) {
        const uint32_t base = sb + s * STG;
#pragma unroll
        for (int i = 0; i < 2; i++) {
            const int c   = tid + i * 256;
            const int row = c >> 2, kc = c & 3;
            const uint32_t doff = (uint32_t)(row * 80 + kc * 16);
            const size_t   soff = (size_t)row * K + k0 + kc * 8;
            CP16(base + 0 * ARR + doff, (const void*)(aH + soff));
            CP16(base + 1 * ARR + doff, (const void*)(aL + soff));
            CP16(base + 2 * ARR + doff, (const void*)(bH + soff));
            if (TERMS == 3)
                CP16(base + 3 * ARR + doff, (const void*)(bL + soff));
        }
    };

    load_stage(0, 0);
    CP_COMMIT();

    for (int c = 0; c < nc; c++) {
        if (c + 1 < nc) {
            load_stage((c + 1) & 1, (c + 1) << 5);
            CP_COMMIT();
            CP_WAIT1();
        } else {
            CP_WAIT0();
        }
        __syncthreads();

        const uint32_t s0 = sb + (c & 1) * STG;
#pragma unroll
        for (int ks = 0; ks < 2; ks++) {
            uint32_t ah[4][4], al[4][4];
#pragma unroll
            for (int mi = 0; mi < 4; mi++) {
                const uint32_t ad = s0 +
                    (uint32_t)((wm * 64 + mi * 16 + (lane & 15)) * 80 + ks * 32 + (lane >> 4) * 16);
                ldm_x4(ah[mi], ad);
                ldm_x4(al[mi], ad + ARR);
            }
#pragma unroll
            for (int bi = 0; bi < 2; bi++) {
                const uint32_t bd = s0 + 2 * ARR +
                    (uint32_t)((wn * 32 + bi * 16 + (lane & 15)) * 80 + ks * 32 + (lane >> 4) * 16);
                uint32_t bh[4], bl[4];
                ldm_x4(bh, bd);
                if (TERMS == 3) ldm_x4(bl, bd + ARR);
#pragma unroll
                for (int n2 = 0; n2 < 2; n2++) {
                    const int ni = bi * 2 + n2;
                    uint32_t bbh[2] = { bh[n2], bh[2 + n2] };
                    if (TERMS == 3) {
                        uint32_t bbl[2] = { bl[n2], bl[2 + n2] };
#pragma unroll
                        for (int mi = 0; mi < 4; mi++) mma_bf16(acc[mi][ni], ah[mi], bbh);  // hh
#pragma unroll
                        for (int mi = 0; mi < 4; mi++) mma_bf16(acc[mi][ni], al[mi], bbh);  // lh
#pragma unroll
                        for (int mi = 0; mi < 4; mi++) mma_bf16(acc[mi][ni], ah[mi], bbl);  // hl
                    } else {
#pragma unroll
                        for (int mi = 0; mi < 4; mi++) mma_f16(acc[mi][ni], ah[mi], bbh);   // hh
#pragma unroll
                        for (int mi = 0; mi < 4; mi++) mma_f16(acc[mi][ni], al[mi], bbh);   // lh
                    }
                }
            }
        }
        __syncthreads();
    }

    // ---- epilogue ----
    const int r  = lane >> 2;
    const int cq = (lane & 3) * 2;
#pragma unroll
    for (int mi = 0; mi < 4; mi++) {
        const int row0 = m0 + wm * 64 + mi * 16 + r;   // second half: row0+8
        float rs0 = 0.f, rs1 = 0.f;
#pragma unroll
        for (int ni = 0; ni < 4; ni++) {
            const int col = n0 + wn * 32 + ni * 8 + cq;
            float v00 = acc[mi][ni][0], v01 = acc[mi][ni][1];
            float v10 = acc[mi][ni][2], v11 = acc[mi][ni][3];
            if (MODE == 0) {
                const size_t o0 = (size_t)row0 * ldOut + col;
                const size_t o1 = (size_t)(row0 + 8) * ldOut + col;
                if (z == 0) {          // Q: fp16 split
                    store_split2_h(outH + o0, outL + o0, v00, v01);
                    store_split2_h(outH + o1, outL + o1, v10, v11);
                } else {               // K: fp16 hi only
                    store2_h(outH2 + o0, v00, v01);
                    store2_h(outH2 + o1, v10, v11);
                }
            } else if (MODE == 3) {    // V^T: rows=d, cols=(b,s) hi only
                const int b = col >> 12, s = col & 4095;
                const size_t o0 = (size_t)b * DIM * SEQ + (size_t)row0 * SEQ + s;
                const size_t o1 = o0 + (size_t)8 * SEQ;
                store2_h(outH + o0, v00, v01);
                store2_h(outH + o1, v10, v11);
            } else if (MODE == 4) {    // scores: exp + fp16 split + row sums
                float e00 = __expf(v00 * alpha), e01 = __expf(v01 * alpha);
                float e10 = __expf(v10 * alpha), e11 = __expf(v11 * alpha);
                rs0 += e00 + e01;
                rs1 += e10 + e11;
                const size_t base = (size_t)z * SEQ * SEQ;
                const size_t o0 = base + (size_t)row0 * SEQ + col;
                const size_t o1 = base + (size_t)(row0 + 8) * SEQ + col;
                store_split2_h(outH + o0, outL + o0, e00, e01);
                store_split2_h(outH + o1, outL + o1, e10, e11);
            } else {                   // MODE 1: context, normalized fp32 out
                const float s0 = rowscale[z * SEQ + row0];
                const float s1 = rowscale[z * SEQ + row0 + 8];
                float* o0 = outF + z * strideOut + (size_t)row0 * ldOut + col;
                float* o1 = outF + z * strideOut + (size_t)(row0 + 8) * ldOut + col;
                *(float2*)o0 = make_float2(v00 * s0, v01 * s0);
                *(float2*)o1 = make_float2(v10 * s1, v11 * s1);
            }
        }
        if (MODE == 4) {
            rs0 += __shfl_xor_sync(0xffffffffu, rs0, 1);
            rs0 += __shfl_xor_sync(0xffffffffu, rs0, 2);
            rs1 += __shfl_xor_sync(0xffffffffu, rs1, 1);
            rs1 += __shfl_xor_sync(0xffffffffu, rs1, 2);
            if ((lane & 3) == 0) {
                atomicAdd(&gsum[z * SEQ + row0], rs0);
                atomicAdd(&gsum[z * SEQ + row0 + 8], rs1);
            }
        }
    }
}

// ---------------------------------------------------------------------------
// prep kernels
// ---------------------------------------------------------------------------
__global__ void split_f32(const float* __restrict__ in, bf16* __restrict__ h,
                          bf16* __restrict__ l, int n4)
{
    int i = blockIdx.x * blockDim.x + threadIdx.x;
    if (i >= n4) return;
    float4 v = ((const float4*)in)[i];
    bf16 h0 = __float2bfloat16(v.x), h1 = __float2bfloat16(v.y);
    bf16 h2 = __float2bfloat16(v.z), h3 = __float2bfloat16(v.w);
    __nv_bfloat162 hp0, hp1, lp0, lp1;
    hp0.x = h0; hp0.y = h1; hp1.x = h2; hp1.y = h3;
    lp0.x = __float2bfloat16(v.x - __bfloat162float(h0));
    lp0.y = __float2bfloat16(v.y - __bfloat162float(h1));
    lp1.x = __float2bfloat16(v.z - __bfloat162float(h2));
    lp1.y = __float2bfloat16(v.w - __bfloat162float(h3));
    ((__nv_bfloat162*)h)[i * 2 + 0] = hp0;
    ((__nv_bfloat162*)h)[i * 2 + 1] = hp1;
    ((__nv_bfloat162*)l)[i * 2 + 0] = lp0;
    ((__nv_bfloat162*)l)[i * 2 + 1] = lp1;
}

// all three weight transposes in one launch (z = blockIdx.y)
__global__ void transpose_split_w3(const float* __restrict__ Wq,
                                   const float* __restrict__ Wk,
                                   const float* __restrict__ Wv,
                                   bf16* __restrict__ th, bf16* __restrict__ tl)
{
    int id = blockIdx.x * blockDim.x + threadIdx.x;   // 512*512
    int z  = blockIdx.y;
    if (id >= DIM * DIM) return;
    const float* W = (z == 0) ? Wq : (z == 1) ? Wk : Wv;
    int k = id >> 9, n = id & 511;
    float v = W[id];
    bf16 h = __float2bfloat16(v);
    bf16 l = __float2bfloat16(v - __bfloat162float(h));
    th[(size_t)z * DIM * DIM + n * DIM + k] = h;
    tl[(size_t)z * DIM * DIM + n * DIM + k] = l;
}

__global__ void zero_sums(float* __restrict__ s)
{
    int i = blockIdx.x * blockDim.x + threadIdx.x;
    if (i < ROWS) s[i] = 0.f;
}

__global__ void invert_sums(const float* __restrict__ s, float* __restrict__ inv)
{
    int i = blockIdx.x * blockDim.x + threadIdx.x;
    if (i < ROWS) inv[i] = 1.0f / s[i];
}

// ---------------------------------------------------------------------------
extern "C" void kernel_launch(void* const* d_in, const int* in_sizes, int n_in,
                              void* d_out, int out_size)
{
    const float* x  = (const float*)d_in[0];
    const float* Wq = (const float*)d_in[1];
    const float* Wk = (const float*)d_in[2];
    const float* Wv = (const float*)d_in[3];
    float* out = (float*)d_out;

    bf16 *xh, *xl, *wth, *wtl;
    __half *Qh, *Ql, *Kh, *Vth, *Ph, *Pl;
    float *sum, *inv;
    cudaGetSymbolAddress((void**)&xh,  g_xh);  cudaGetSymbolAddress((void**)&xl,  g_xl);
    cudaGetSymbolAddress((void**)&wth, g_wth); cudaGetSymbolAddress((void**)&wtl, g_wtl);
    cudaGetSymbolAddress((void**)&Qh,  g_Qh);  cudaGetSymbolAddress((void**)&Ql,  g_Ql);
    cudaGetSymbolAddress((void**)&Kh,  g_Kh);
    cudaGetSymbolAddress((void**)&Vth, g_Vth);
    cudaGetSymbolAddress((void**)&Ph,  g_Ph);  cudaGetSymbolAddress((void**)&Pl,  g_Pl);
    cudaGetSymbolAddress((void**)&sum, g_sum);
    cudaGetSymbolAddress((void**)&inv, g_inv);

    const int SMEM3 = 2 * 4 * ARR;   // 3-term stages (81920)
    const int SMEM2 = 2 * 3 * ARR;   // 2-term stages (61440)
    cudaFuncSetAttribute(mma_gemm<0>, cudaFuncAttributeMaxDynamicSharedMemorySize, SMEM3);
    cudaFuncSetAttribute(mma_gemm<3>, cudaFuncAttributeMaxDynamicSharedMemorySize, SMEM3);
    cudaFuncSetAttribute(mma_gemm<4>, cudaFuncAttributeMaxDynamicSharedMemorySize, SMEM2);
    cudaFuncSetAttribute(mma_gemm<1>, cudaFuncAttributeMaxDynamicSharedMemorySize, SMEM2);

    const float inv_sqrt_d = 0.04419417382415922f;  // 1/sqrt(512)

    // 0) prep: zero row sums, split x, transpose+split all weights
    zero_sums<<<(ROWS + 255) / 256, 256>>>(sum);
    split_f32<<<(ROWS * DIM / 4 + 255) / 256, 256>>>(x, xh, xl, ROWS * DIM / 4);
    {
        dim3 g((DIM * DIM + 255) / 256, 3);
        transpose_split_w3<<<g, 256>>>(Wq, Wk, Wv, wth, wtl);
    }

    // 1) Q + K projections in one launch (z=0 -> Q split, z=1 -> K hi)
    {
        dim3 g(DIM / 128, ROWS / 128, 2);
        mma_gemm<0><<<g, 256, SMEM3>>>(
            (const uint16_t*)xh, (const uint16_t*)xl,
            (const uint16_t*)wth, (const uint16_t*)wtl,
            DIM, 0, (size_t)DIM * DIM,
            1.f, nullptr, nullptr, nullptr, 0, DIM, Qh, Ql, Kh);
    }
    // V projection -> V^T hi only (A = Wv^T, B = x)
    {
        dim3 g(ROWS / 128, DIM / 128, 1);
        mma_gemm<3><<<g, 256, SMEM3>>>(
            (const uint16_t*)(wth + 2 * DIM * DIM), (const uint16_t*)(wtl + 2 * DIM * DIM),
            (const uint16_t*)xh, (const uint16_t*)xl,
            DIM, 0, 0,
            1.f, nullptr, nullptr, nullptr, 0, 0, Vth, nullptr, nullptr);
    }

    // 2) fused scores + softmax-exp (fp16 2-term): P = exp(QK^T/sqrt(d))
    {
        dim3 g(SEQ / 128, SEQ / 128, BATCH);
        mma_gemm<4><<<g, 256, SMEM2>>>(
            (const uint16_t*)Qh, (const uint16_t*)Ql, (const uint16_t*)Kh, nullptr,
            DIM, (size_t)SEQ * DIM, (size_t)SEQ * DIM,
            inv_sqrt_d, nullptr, sum, nullptr, 0, 0, Ph, Pl, nullptr);
    }

    // 3) invert row sums
    invert_sums<<<(ROWS + 255) / 256, 256>>>(sum, inv);

    // 4) context = diag(1/rowsum) * (P @ V)  (fp16 2-term, B = V^T hi)
    {
        dim3 g(DIM / 128, SEQ / 128, BATCH);
        mma_gemm<1><<<g, 256, SMEM2>>>(
            (const uint16_t*)Ph, (const uint16_t*)Pl, (const uint16_t*)Vth, nullptr,
            SEQ, (size_t)SEQ * SEQ, (size_t)DIM * SEQ,
            1.f, inv, nullptr, out, (size_t)SEQ * DIM, DIM, nullptr, nullptr, nullptr);
    }
}

// round 8
// speedup vs baseline: 2.9886x; 1.4958x over previous
#include <cuda_runtime.h>
#include <cuda_bf16.h>
#include <cuda_fp16.h>
#include <math.h>
#include <stdint.h>

// Problem constants
#define BATCH 2
#define SEQ   4096
#define DIM   512
#define ROWS  (BATCH * SEQ)          // 8192

typedef __nv_bfloat16 bf16;

// ---------------------------------------------------------------------------
// Device scratch (static globals — no allocations)
// ---------------------------------------------------------------------------
__device__ bf16   g_xh[ROWS * DIM],  g_xl[ROWS * DIM];          // x split (proj A operand)
__device__ bf16   g_wth[3 * DIM * DIM], g_wtl[3 * DIM * DIM];   // W^T hi/lo (proj B operand)
__device__ __half g_Qh[ROWS * DIM];                              // Q fp16 (scores A)
__device__ __half g_Kh[ROWS * DIM];                              // K fp16 (scores B)
__device__ __half g_Vth[(size_t)BATCH * DIM * SEQ];              // V^T fp16 (context B)
__device__ __half g_Ph[(size_t)BATCH * SEQ * SEQ];               // P fp16 (context A)
__device__ float  g_sum[ROWS];       // exp row sums (atomic)
__device__ float  g_inv[ROWS];       // 1/rowsum

// ---------------------------------------------------------------------------
// helpers (baseline sm_80+ PTX only — NO tcgen05 / 'a'-gated features)
// ---------------------------------------------------------------------------
__device__ __forceinline__ uint32_t smem_u32(const void* p) {
    uint32_t a;
    asm("{ .reg .u64 t; cvta.to.shared.u64 t, %1; cvt.u32.u64 %0, t; }" : "=r"(a) : "l"(p));
    return a;
}
#define CP16(dst, src) \
    asm volatile("cp.async.cg.shared.global [%0], [%1], 16;" :: "r"(dst), "l"(src))
#define CP_COMMIT() asm volatile("cp.async.commit_group;" ::: "memory")
#define CP_WAIT1()  asm volatile("cp.async.wait_group 1;" ::: "memory")
#define CP_WAIT0()  asm volatile("cp.async.wait_group 0;" ::: "memory")

__device__ __forceinline__ void ldm_x4(uint32_t* r, uint32_t addr) {
    asm volatile("ldmatrix.sync.aligned.m8n8.x4.shared.b16 {%0,%1,%2,%3}, [%4];"
        : "=r"(r[0]), "=r"(r[1]), "=r"(r[2]), "=r"(r[3]) : "r"(addr));
}
__device__ __forceinline__ void mma_bf16(float* c, const uint32_t* a, const uint32_t* b) {
    asm volatile(
        "mma.sync.aligned.m16n8k16.row.col.f32.bf16.bf16.f32 "
        "{%0,%1,%2,%3}, {%4,%5,%6,%7}, {%8,%9}, {%0,%1,%2,%3};"
        : "+f"(c[0]), "+f"(c[1]), "+f"(c[2]), "+f"(c[3])
        : "r"(a[0]), "r"(a[1]), "r"(a[2]), "r"(a[3]), "r"(b[0]), "r"(b[1]));
}
__device__ __forceinline__ void mma_f16(float* c, const uint32_t* a, const uint32_t* b) {
    asm volatile(
        "mma.sync.aligned.m16n8k16.row.col.f32.f16.f16.f32 "
        "{%0,%1,%2,%3}, {%4,%5,%6,%7}, {%8,%9}, {%0,%1,%2,%3};"
        : "+f"(c[0]), "+f"(c[1]), "+f"(c[2]), "+f"(c[3])
        : "r"(a[0]), "r"(a[1]), "r"(a[2]), "r"(a[3]), "r"(b[0]), "r"(b[1]));
}
__device__ __forceinline__ void store2_h(__half* o, float a, float b) {
    *(__half2*)o = __halves2half2(__float2half_rn(a), __float2half_rn(b));
}

// smem: per-array 128 rows x 80 bytes
#define ARR 10240

// ---------------------------------------------------------------------------
// NT GEMM via mma.sync: C[128x128] = sum_k A[m,k]*B[n,k] (16-bit operands).
// MODE 0: bf16 3-term proj -> fp16 out; z=0 -> Q (outH), z=1 -> K (outH2)
// MODE 3: bf16 3-term proj (A=W^T, B=x) -> V^T fp16 [b][d][s]
// MODE 4: fp16 1-term scores: e=exp(val*alpha) -> fp16 + atomic row sums
// MODE 1: fp16 1-term context: outF = val * rowscale[z*SEQ+row]
// ---------------------------------------------------------------------------
template <int MODE>
__global__ __launch_bounds__(256, 2)
void mma_gemm(const uint16_t* __restrict__ Ah, const uint16_t* __restrict__ Al,
              const uint16_t* __restrict__ Bh, const uint16_t* __restrict__ Bl,
              int K, size_t strideA, size_t strideB,
              float alpha, const float* __restrict__ rowscale, float* gsum,
              float* __restrict__ outF, size_t strideOut, int ldOut,
              __half* __restrict__ outH, __half* __restrict__ outH2)
{
    constexpr bool T3   = (MODE == 0 || MODE == 3);   // 3-term bf16 split
    constexpr int  NARR = T3 ? 4 : 2;
    constexpr int  STG  = NARR * ARR;
    constexpr int  OFFB = T3 ? 2 * ARR : ARR;         // Bh offset within stage

    extern __shared__ char smem[];
    const uint32_t sb = smem_u32(smem);
    const int tid  = threadIdx.x;
    const int lane = tid & 31;
    const int wid  = tid >> 5;
    const int wm   = wid & 1;         // 2 warps along M (64 rows each)
    const int wn   = wid >> 1;        // 4 warps along N (32 cols each)
    const int m0 = blockIdx.y * 128;
    const int n0 = blockIdx.x * 128;
    const int z  = blockIdx.z;

    const uint16_t* aH = Ah + z * strideA + (size_t)m0 * K;
    const uint16_t* aL = T3 ? (Al + z * strideA + (size_t)m0 * K) : nullptr;
    const uint16_t* bH = Bh + z * strideB + (size_t)n0 * K;
    const uint16_t* bL = T3 ? (Bl + z * strideB + (size_t)n0 * K) : nullptr;

    float acc[4][4][4];
#pragma unroll
    for (int i = 0; i < 4; i++)
#pragma unroll
        for (int j = 0; j < 4; j++)
#pragma unroll
            for (int q = 0; q < 4; q++) acc[i][j][q] = 0.f;

    const int nc = K >> 5;   // 32-wide k chunks

    auto load_stage = [&](int s, int k0) {
        const uint32_t base = sb + s * STG;
#pragma unroll
        for (int i = 0; i < 2; i++) {
            const int c   = tid + i * 256;
            const int row = c >> 2, kc = c & 3;
            const uint32_t doff = (uint32_t)(row * 80 + kc * 16);
            const size_t   soff = (size_t)row * K + k0 + kc * 8;
            CP16(base + doff, (const void*)(aH + soff));
            CP16(base + OFFB + doff, (const void*)(bH + soff));
            if (T3) {
                CP16(base + 1 * ARR + doff, (const void*)(aL + soff));
                CP16(base + 3 * ARR + doff, (const void*)(bL + soff));
            }
        }
    };

    load_stage(0, 0);
    CP_COMMIT();

    for (int c = 0; c < nc; c++) {
        if (c + 1 < nc) {
            load_stage((c + 1) & 1, (c + 1) << 5);
            CP_COMMIT();
            CP_WAIT1();
        } else {
            CP_WAIT0();
        }
        __syncthreads();

        const uint32_t s0 = sb + (c & 1) * STG;
#pragma unroll
        for (int ks = 0; ks < 2; ks++) {
            uint32_t ah[4][4], al[4][4];
#pragma unroll
            for (int mi = 0; mi < 4; mi++) {
                const uint32_t ad = s0 +
                    (uint32_t)((wm * 64 + mi * 16 + (lane & 15)) * 80 + ks * 32 + (lane >> 4) * 16);
                ldm_x4(ah[mi], ad);
                if (T3) ldm_x4(al[mi], ad + ARR);
            }
#pragma unroll
            for (int bi = 0; bi < 2; bi++) {
                const uint32_t bd = s0 + OFFB +
                    (uint32_t)((wn * 32 + bi * 16 + (lane & 15)) * 80 + ks * 32 + (lane >> 4) * 16);
                uint32_t bh[4], bl[4];
                ldm_x4(bh, bd);
                if (T3) ldm_x4(bl, bd + ARR);
#pragma unroll
                for (int n2 = 0; n2 < 2; n2++) {
                    const int ni = bi * 2 + n2;
                    uint32_t bbh[2] = { bh[n2], bh[2 + n2] };
                    if (T3) {
                        uint32_t bbl[2] = { bl[n2], bl[2 + n2] };
#pragma unroll
                        for (int mi = 0; mi < 4; mi++) mma_bf16(acc[mi][ni], ah[mi], bbh);  // hh
#pragma unroll
                        for (int mi = 0; mi < 4; mi++) mma_bf16(acc[mi][ni], al[mi], bbh);  // lh
#pragma unroll
                        for (int mi = 0; mi < 4; mi++) mma_bf16(acc[mi][ni], ah[mi], bbl);  // hl
                    } else {
#pragma unroll
                        for (int mi = 0; mi < 4; mi++) mma_f16(acc[mi][ni], ah[mi], bbh);   // hh
                    }
                }
            }
        }
        __syncthreads();
    }

    // ---- epilogue ----
    const int r  = lane >> 2;
    const int cq = (lane & 3) * 2;
#pragma unroll
    for (int mi = 0; mi < 4; mi++) {
        const int row0 = m0 + wm * 64 + mi * 16 + r;   // second half: row0+8
        float rs0 = 0.f, rs1 = 0.f;
#pragma unroll
        for (int ni = 0; ni < 4; ni++) {
            const int col = n0 + wn * 32 + ni * 8 + cq;
            float v00 = acc[mi][ni][0], v01 = acc[mi][ni][1];
            float v10 = acc[mi][ni][2], v11 = acc[mi][ni][3];
            if (MODE == 0) {
                const size_t o0 = (size_t)row0 * ldOut + col;
                const size_t o1 = (size_t)(row0 + 8) * ldOut + col;
                __half* dst = (z == 0) ? outH : outH2;
                store2_h(dst + o0, v00, v01);
                store2_h(dst + o1, v10, v11);
            } else if (MODE == 3) {    // V^T: rows=d, cols=(b,s)
                const int b = col >> 12, s = col & 4095;
                const size_t o0 = (size_t)b * DIM * SEQ + (size_t)row0 * SEQ + s;
                const size_t o1 = o0 + (size_t)8 * SEQ;
                store2_h(outH + o0, v00, v01);
                store2_h(outH + o1, v10, v11);
            } else if (MODE == 4) {    // scores: exp + fp16 + row sums
                float e00 = __expf(v00 * alpha), e01 = __expf(v01 * alpha);
                float e10 = __expf(v10 * alpha), e11 = __expf(v11 * alpha);
                rs0 += e00 + e01;
                rs1 += e10 + e11;
                const size_t base = (size_t)z * SEQ * SEQ;
                const size_t o0 = base + (size_t)row0 * SEQ + col;
                const size_t o1 = base + (size_t)(row0 + 8) * SEQ + col;
                store2_h(outH + o0, e00, e01);
                store2_h(outH + o1, e10, e11);
            } else {                   // MODE 1: context, normalized fp32 out
                const float s0 = rowscale[z * SEQ + row0];
                const float s1 = rowscale[z * SEQ + row0 + 8];
                float* o0 = outF + z * strideOut + (size_t)row0 * ldOut + col;
                float* o1 = outF + z * strideOut + (size_t)(row0 + 8) * ldOut + col;
                *(float2*)o0 = make_float2(v00 * s0, v01 * s0);
                *(float2*)o1 = make_float2(v10 * s1, v11 * s1);
            }
        }
        if (MODE == 4) {
            rs0 += __shfl_xor_sync(0xffffffffu, rs0, 1);
            rs0 += __shfl_xor_sync(0xffffffffu, rs0, 2);
            rs1 += __shfl_xor_sync(0xffffffffu, rs1, 1);
            rs1 += __shfl_xor_sync(0xffffffffu, rs1, 2);
            if ((lane & 3) == 0) {
                atomicAdd(&gsum[z * SEQ + row0], rs0);
                atomicAdd(&gsum[z * SEQ + row0 + 8], rs1);
            }
        }
    }
}

// ---------------------------------------------------------------------------
// prep kernels
// ---------------------------------------------------------------------------
__global__ void split_f32(const float* __restrict__ in, bf16* __restrict__ h,
                          bf16* __restrict__ l, int n4)
{
    int i = blockIdx.x * blockDim.x + threadIdx.x;
    if (i >= n4) return;
    float4 v = ((const float4*)in)[i];
    bf16 h0 = __float2bfloat16(v.x), h1 = __float2bfloat16(v.y);
    bf16 h2 = __float2bfloat16(v.z), h3 = __float2bfloat16(v.w);
    __nv_bfloat162 hp0, hp1, lp0, lp1;
    hp0.x = h0; hp0.y = h1; hp1.x = h2; hp1.y = h3;
    lp0.x = __float2bfloat16(v.x - __bfloat162float(h0));
    lp0.y = __float2bfloat16(v.y - __bfloat162float(h1));
    lp1.x = __float2bfloat16(v.z - __bfloat162float(h2));
    lp1.y = __float2bfloat16(v.w - __bfloat162float(h3));
    ((__nv_bfloat162*)h)[i * 2 + 0] = hp0;
    ((__nv_bfloat162*)h)[i * 2 + 1] = hp1;
    ((__nv_bfloat162*)l)[i * 2 + 0] = lp0;
    ((__nv_bfloat162*)l)[i * 2 + 1] = lp1;
}

// all three weight transposes in one launch (z = blockIdx.y)
__global__ void transpose_split_w3(const float* __restrict__ Wq,
                                   const float* __restrict__ Wk,
                                   const float* __restrict__ Wv,
                                   bf16* __restrict__ th, bf16* __restrict__ tl)
{
    int id = blockIdx.x * blockDim.x + threadIdx.x;   // 512*512
    int z  = blockIdx.y;
    if (id >= DIM * DIM) return;
    const float* W = (z == 0) ? Wq : (z == 1) ? Wk : Wv;
    int k = id >> 9, n = id & 511;
    float v = W[id];
    bf16 h = __float2bfloat16(v);
    bf16 l = __float2bfloat16(v - __bfloat162float(h));
    th[(size_t)z * DIM * DIM + n * DIM + k] = h;
    tl[(size_t)z * DIM * DIM + n * DIM + k] = l;
}

__global__ void zero_sums(float* __restrict__ s)
{
    int i = blockIdx.x * blockDim.x + threadIdx.x;
    if (i < ROWS) s[i] = 0.f;
}

__global__ void invert_sums(const float* __restrict__ s, float* __restrict__ inv)
{
    int i = blockIdx.x * blockDim.x + threadIdx.x;
    if (i < ROWS) inv[i] = 1.0f / s[i];
}

// ---------------------------------------------------------------------------
extern "C" void kernel_launch(void* const* d_in, const int* in_sizes, int n_in,
                              void* d_out, int out_size)
{
    const float* x  = (const float*)d_in[0];
    const float* Wq = (const float*)d_in[1];
    const float* Wk = (const float*)d_in[2];
    const float* Wv = (const float*)d_in[3];
    float* out = (float*)d_out;

    bf16 *xh, *xl, *wth, *wtl;
    __half *Qh, *Kh, *Vth, *Ph;
    float *sum, *inv;
    cudaGetSymbolAddress((void**)&xh,  g_xh);  cudaGetSymbolAddress((void**)&xl,  g_xl);
    cudaGetSymbolAddress((void**)&wth, g_wth); cudaGetSymbolAddress((void**)&wtl, g_wtl);
    cudaGetSymbolAddress((void**)&Qh,  g_Qh);
    cudaGetSymbolAddress((void**)&Kh,  g_Kh);
    cudaGetSymbolAddress((void**)&Vth, g_Vth);
    cudaGetSymbolAddress((void**)&Ph,  g_Ph);
    cudaGetSymbolAddress((void**)&sum, g_sum);
    cudaGetSymbolAddress((void**)&inv, g_inv);

    const int SMEM3 = 2 * 4 * ARR;   // 3-term stages (81920)
    const int SMEM1 = 2 * 2 * ARR;   // 1-term stages (40960)
    cudaFuncSetAttribute(mma_gemm<0>, cudaFuncAttributeMaxDynamicSharedMemorySize, SMEM3);
    cudaFuncSetAttribute(mma_gemm<3>, cudaFuncAttributeMaxDynamicSharedMemorySize, SMEM3);
    cudaFuncSetAttribute(mma_gemm<4>, cudaFuncAttributeMaxDynamicSharedMemorySize, SMEM1);
    cudaFuncSetAttribute(mma_gemm<1>, cudaFuncAttributeMaxDynamicSharedMemorySize, SMEM1);

    const float inv_sqrt_d = 0.04419417382415922f;  // 1/sqrt(512)

    // 0) prep: zero row sums, split x, transpose+split all weights
    zero_sums<<<(ROWS + 255) / 256, 256>>>(sum);
    split_f32<<<(ROWS * DIM / 4 + 255) / 256, 256>>>(x, xh, xl, ROWS * DIM / 4);
    {
        dim3 g((DIM * DIM + 255) / 256, 3);
        transpose_split_w3<<<g, 256>>>(Wq, Wk, Wv, wth, wtl);
    }

    // 1) Q + K projections in one launch (z selects weight + destination)
    {
        dim3 g(DIM / 128, ROWS / 128, 2);
        mma_gemm<0><<<g, 256, SMEM3>>>(
            (const uint16_t*)xh, (const uint16_t*)xl,
            (const uint16_t*)wth, (const uint16_t*)wtl,
            DIM, 0, (size_t)DIM * DIM,
            1.f, nullptr, nullptr, nullptr, 0, DIM, Qh, Kh);
    }
    // V projection -> V^T (A = Wv^T, B = x)
    {
        dim3 g(ROWS / 128, DIM / 128, 1);
        mma_gemm<3><<<g, 256, SMEM3>>>(
            (const uint16_t*)(wth + 2 * DIM * DIM), (const uint16_t*)(wtl + 2 * DIM * DIM),
            (const uint16_t*)xh, (const uint16_t*)xl,
            DIM, 0, 0,
            1.f, nullptr, nullptr, nullptr, 0, 0, Vth, nullptr);
    }

    // 2) fused scores + softmax-exp (fp16 1-term): P = exp(QK^T/sqrt(d))
    {
        dim3 g(SEQ / 128, SEQ / 128, BATCH);
        mma_gemm<4><<<g, 256, SMEM1>>>(
            (const uint16_t*)Qh, nullptr, (const uint16_t*)Kh, nullptr,
            DIM, (size_t)SEQ * DIM, (size_t)SEQ * DIM,
            inv_sqrt_d, nullptr, sum, nullptr, 0, 0, Ph, nullptr);
    }

    // 3) invert row sums
    invert_sums<<<(ROWS + 255) / 256, 256>>>(sum, inv);

    // 4) context = diag(1/rowsum) * (P @ V)  (fp16 1-term, B = V^T)
    {
        dim3 g(DIM / 128, SEQ / 128, BATCH);
        mma_gemm<1><<<g, 256, SMEM1>>>(
            (const uint16_t*)Ph, nullptr, (const uint16_t*)Vth, nullptr,
            SEQ, (size_t)SEQ * SEQ, (size_t)DIM * SEQ,
            1.f, inv, nullptr, out, (size_t)SEQ * DIM, DIM, nullptr, nullptr);
    }
}